// round 1
// baseline (speedup 1.0000x reference)
#include <cuda_runtime.h>

#define NN 20000
#define EE 500000
#define KK 48

// ---------------- device scratch (no allocations allowed) ----------------
__device__ __align__(16) float          g_basis[EE * 8];
__device__ __align__(16) unsigned char  g_kidx [EE * 8];
__device__ __align__(16) float          g_acc1 [NN * KK];            // layer1 buckets (c_in=1)
__device__ __align__(16) float          g_acc2 [NN * KK * 32];       // layer2 buckets
__device__ __align__(16) float          g_acc3 [(size_t)NN * KK * 64]; // layer3 buckets
__device__ __align__(16) float          g_h1   [NN * 32];
__device__ __align__(16) float          g_h2   [NN * 64];

// ---------------- helpers ----------------
__device__ __forceinline__ void red_add_v4(float* p, float a, float b, float c, float d) {
    asm volatile("red.global.add.v4.f32 [%0], {%1,%2,%3,%4};"
                 :: "l"(p), "f"(a), "f"(b), "f"(c), "f"(d) : "memory");
}

// ---------------- basis / kernel-index precompute ----------------
__global__ void precompute_kernel(const float* __restrict__ pseudo, int E) {
    int e = blockIdx.x * blockDim.x + threadIdx.x;
    if (e >= E) return;
    const int ks0 = 3, ks1 = 8, ks2 = 2;
    float fr[3]; int lo[3];
    const int ksm1[3] = {ks0 - 1, ks1 - 1, ks2 - 1};
#pragma unroll
    for (int d = 0; d < 3; d++) {
        float u = pseudo[e * 3 + d] * (1.0f / 4.5f);
        u = fminf(fmaxf(u, 0.0f), 1.0f);
        float pos = u * (float)ksm1[d];
        float fl = floorf(pos);
        fr[d] = pos - fl;
        lo[d] = (int)fl;
    }
    float b[8]; unsigned char kx[8];
#pragma unroll
    for (int s = 0; s < 8; s++) {
        float w = 1.0f; int idx[3];
#pragma unroll
        for (int d = 0; d < 3; d++) {
            int bit = (s >> d) & 1;
            int id = lo[d] + bit;
            if (id > ksm1[d]) id = ksm1[d];
            idx[d] = id;
            w *= bit ? fr[d] : (1.0f - fr[d]);
        }
        b[s] = w;
        kx[s] = (unsigned char)(idx[0] * 16 + idx[1] * 2 + idx[2]);
    }
    *(float4*)&g_basis[e * 8]     = make_float4(b[0], b[1], b[2], b[3]);
    *(float4*)&g_basis[e * 8 + 4] = make_float4(b[4], b[5], b[6], b[7]);
    uchar4* kp = (uchar4*)&g_kidx[e * 8];
    kp[0] = make_uchar4(kx[0], kx[1], kx[2], kx[3]);
    kp[1] = make_uchar4(kx[4], kx[5], kx[6], kx[7]);
}

// ---------------- zero accumulators ----------------
__global__ void zero_all_kernel() {
    size_t i = (size_t)blockIdx.x * blockDim.x + threadIdx.x;
    size_t stride = (size_t)gridDim.x * blockDim.x;
    float4 z = make_float4(0.f, 0.f, 0.f, 0.f);
    for (size_t j = i; j < (size_t)(NN * KK) / 4; j += stride)          ((float4*)g_acc1)[j] = z;
    for (size_t j = i; j < (size_t)NN * KK * 32 / 4; j += stride)       ((float4*)g_acc2)[j] = z;
    for (size_t j = i; j < (size_t)NN * KK * 64 / 4; j += stride)       ((float4*)g_acc3)[j] = z;
}

// ---------------- layer-1 scatter (c_in = 1) ----------------
__global__ void scatter1_kernel(const int* __restrict__ ei, const float* __restrict__ x, int E) {
    int e = blockIdx.x * blockDim.x + threadIdx.x;
    if (e >= E) return;
    int src = ei[e], dst = ei[E + e];
    float xs = __ldg(&x[src]);
    float4 b0 = *(const float4*)&g_basis[e * 8];
    float4 b1 = *(const float4*)&g_basis[e * 8 + 4];
    uchar4 k0 = ((const uchar4*)&g_kidx[e * 8])[0];
    uchar4 k1 = ((const uchar4*)&g_kidx[e * 8])[1];
    float* base = &g_acc1[dst * KK];
    atomicAdd(base + k0.x, b0.x * xs);
    atomicAdd(base + k0.y, b0.y * xs);
    atomicAdd(base + k0.z, b0.z * xs);
    atomicAdd(base + k0.w, b0.w * xs);
    atomicAdd(base + k1.x, b1.x * xs);
    atomicAdd(base + k1.y, b1.y * xs);
    atomicAdd(base + k1.z, b1.z * xs);
    atomicAdd(base + k1.w, b1.w * xs);
}

// ---------------- layer-1 dense: h1 = relu(acc1 @ W1 + x*root1 + b1) ----------------
__global__ void dense1_kernel(const float* __restrict__ x, const float* __restrict__ W1,
                              const float* __restrict__ root1, const float* __restrict__ b1, int N) {
    int gid = blockIdx.x * blockDim.x + threadIdx.x;
    int n = gid >> 5, o = gid & 31;
    if (n >= N) return;
    float s = x[n] * root1[o] + b1[o];
    const float* a = &g_acc1[n * KK];
#pragma unroll
    for (int k = 0; k < KK; k++) s += a[k] * W1[k * 32 + o];
    g_h1[n * 32 + o] = fmaxf(s, 0.0f);
}

// ---------------- scatter for layers 2/3: acc[dst,k,:] += basis * h[src,:] ----------------
template <int CIN>
__global__ void scatter_kernel(const int* __restrict__ ei, int E) {
    int e = blockIdx.x * blockDim.x + threadIdx.x;
    if (e >= E) return;
    const float* h = (CIN == 32) ? g_h1 : g_h2;
    float* acc = (CIN == 32) ? g_acc2 : g_acc3;
    int src = ei[e], dst = ei[E + e];
    float4 hv[CIN / 4];
    const float4* hp = (const float4*)&h[(size_t)src * CIN];
#pragma unroll
    for (int i = 0; i < CIN / 4; i++) hv[i] = hp[i];
    float4 b0 = *(const float4*)&g_basis[e * 8];
    float4 b1 = *(const float4*)&g_basis[e * 8 + 4];
    float bs[8] = {b0.x, b0.y, b0.z, b0.w, b1.x, b1.y, b1.z, b1.w};
    uchar4 k0 = ((const uchar4*)&g_kidx[e * 8])[0];
    uchar4 k1 = ((const uchar4*)&g_kidx[e * 8])[1];
    int kx[8] = {k0.x, k0.y, k0.z, k0.w, k1.x, k1.y, k1.z, k1.w};
#pragma unroll
    for (int s = 0; s < 8; s++) {
        float w = bs[s];
        float* base = acc + ((size_t)dst * KK + kx[s]) * CIN;
#pragma unroll
        for (int i = 0; i < CIN / 4; i++)
            red_add_v4(base + i * 4, w * hv[i].x, w * hv[i].y, w * hv[i].z, w * hv[i].w);
    }
}

// ---------------- tiled fp32 GEMM: C = relu(A@B + H@R + bias) ----------------
// A = acc buffer [M, KA] (device symbol), B = W [KA, BN]
// H = prev features [M, KH] (device symbol), R = root [KH, BN]
template <int KA, int KH, int BN>
__global__ void __launch_bounds__(256) gemm_kernel(const float* __restrict__ B,
                                                   const float* __restrict__ R,
                                                   const float* __restrict__ bias,
                                                   float* __restrict__ Cout, int M) {
    constexpr int BM = 64, KC = 32, TN = 4;
    constexpr int TM = (BM * BN) / (256 * TN);   // 8 for BN=128, 4 for BN=64
    const float* A = (KA == 1536) ? g_acc2 : g_acc3;
    const float* H = (KA == 1536) ? g_h1 : g_h2;
    float* C = (KA == 1536) ? g_h2 : Cout;

    __shared__ float As[KC][BM];
    __shared__ float Bs[KC][BN];

    int t = threadIdx.x;
    int tx = t % (BN / TN);
    int ty = t / (BN / TN);
    int m0 = blockIdx.x * BM;

    float acc[TM][TN];
#pragma unroll
    for (int i = 0; i < TM; i++)
#pragma unroll
        for (int j = 0; j < TN; j++) acc[i][j] = 0.0f;

    constexpr int CHA = KA / KC;
    constexpr int CH = CHA + KH / KC;
    for (int ch = 0; ch < CH; ch++) {
        const float* Ap; const float* Bp; int lda; int k0;
        if (ch < CHA) { Ap = A; Bp = B; lda = KA; k0 = ch * KC; }
        else          { Ap = H; Bp = R; lda = KH; k0 = (ch - CHA) * KC; }

        // load A tile [BM][KC], stored transposed As[KC][BM]
#pragma unroll
        for (int j = 0; j < 2; j++) {
            int slot = j * 256 + t;          // 512 float4 slots
            int row = slot >> 3;             // KC/4 = 8 float4 per row
            int c4 = slot & 7;
            float4 v = make_float4(0.f, 0.f, 0.f, 0.f);
            int gr = m0 + row;
            if (gr < M) v = *(const float4*)&Ap[(size_t)gr * lda + k0 + c4 * 4];
            As[c4 * 4 + 0][row] = v.x;
            As[c4 * 4 + 1][row] = v.y;
            As[c4 * 4 + 2][row] = v.z;
            As[c4 * 4 + 3][row] = v.w;
        }
        // load B tile [KC][BN]
#pragma unroll
        for (int j = 0; j < BN / 32; j++) {
            int slot = j * 256 + t;          // KC*BN/4 slots
            ((float4*)Bs)[slot] = *(const float4*)&Bp[(size_t)k0 * BN + slot * 4];
        }
        __syncthreads();

#pragma unroll 4
        for (int kk = 0; kk < KC; kk++) {
            float4 b4 = *(const float4*)&Bs[kk][tx * TN];
            float a[TM];
#pragma unroll
            for (int i = 0; i < TM; i++) a[i] = As[kk][ty * TM + i];
#pragma unroll
            for (int i = 0; i < TM; i++) {
                acc[i][0] += a[i] * b4.x;
                acc[i][1] += a[i] * b4.y;
                acc[i][2] += a[i] * b4.z;
                acc[i][3] += a[i] * b4.w;
            }
        }
        __syncthreads();
    }

    float4 bb = *(const float4*)&bias[tx * TN];
#pragma unroll
    for (int i = 0; i < TM; i++) {
        int gr = m0 + ty * TM + i;
        if (gr < M) {
            float4 o;
            o.x = fmaxf(acc[i][0] + bb.x, 0.0f);
            o.y = fmaxf(acc[i][1] + bb.y, 0.0f);
            o.z = fmaxf(acc[i][2] + bb.z, 0.0f);
            o.w = fmaxf(acc[i][3] + bb.w, 0.0f);
            *(float4*)&C[(size_t)gr * BN + tx * TN] = o;
        }
    }
}

// ---------------- in-place log_softmax over 128 cols ----------------
__global__ void lsm_kernel(float* __restrict__ out) {
    int n = blockIdx.x;
    int t = threadIdx.x;
    float v = out[n * 128 + t];
    float m = v;
#pragma unroll
    for (int o = 16; o > 0; o >>= 1) m = fmaxf(m, __shfl_xor_sync(0xffffffffu, m, o));
    __shared__ float sred[4];
    __shared__ float ssum[4];
    int w = t >> 5, l = t & 31;
    if (l == 0) sred[w] = m;
    __syncthreads();
    float M4 = fmaxf(fmaxf(sred[0], sred[1]), fmaxf(sred[2], sred[3]));
    float e = expf(v - M4);
    float s = e;
#pragma unroll
    for (int o = 16; o > 0; o >>= 1) s += __shfl_xor_sync(0xffffffffu, s, o);
    if (l == 0) ssum[w] = s;
    __syncthreads();
    float S = ssum[0] + ssum[1] + ssum[2] + ssum[3];
    out[n * 128 + t] = v - M4 - logf(S);
}

// ---------------- entry ----------------
extern "C" void kernel_launch(void* const* d_in, const int* in_sizes, int n_in,
                              void* d_out, int out_size) {
    const float* x      = (const float*)d_in[0];
    const int*   ei     = (const int*)  d_in[1];
    const float* pseudo = (const float*)d_in[2];
    const float* W1     = (const float*)d_in[3];
    const float* root1  = (const float*)d_in[4];
    const float* b1     = (const float*)d_in[5];
    const float* W2     = (const float*)d_in[6];
    const float* root2  = (const float*)d_in[7];
    const float* b2     = (const float*)d_in[8];
    const float* W3     = (const float*)d_in[9];
    const float* root3  = (const float*)d_in[10];
    const float* b3     = (const float*)d_in[11];
    float* out = (float*)d_out;
    int N = in_sizes[0];
    int E = in_sizes[1] / 2;

    int eb = (E + 255) / 256;
    precompute_kernel<<<eb, 256>>>(pseudo, E);
    zero_all_kernel<<<4096, 256>>>();
    scatter1_kernel<<<eb, 256>>>(ei, x, E);
    dense1_kernel<<<(N * 32 + 255) / 256, 256>>>(x, W1, root1, b1, N);
    scatter_kernel<32><<<(E + 127) / 128, 128>>>(ei, E);
    gemm_kernel<1536, 32, 64><<<(N + 63) / 64, 256>>>(W2, root2, b2, nullptr, N);
    scatter_kernel<64><<<(E + 127) / 128, 128>>>(ei, E);
    gemm_kernel<3072, 64, 128><<<(N + 63) / 64, 256>>>(W3, root3, b3, out, N);
    lsm_kernel<<<N, 128>>>(out);
}

// round 3
// speedup vs baseline: 1.1036x; 1.1036x over previous
#include <cuda_runtime.h>
#include <cuda_bf16.h>
#include <cstdint>

#define NN 20000
#define EE 500000
#define KK 48

// ---------------- device scratch (no allocations allowed) ----------------
__device__ __align__(16) float          g_basis[EE * 8];
__device__ __align__(16) unsigned char  g_kidx [EE * 8];
__device__ __align__(16) float          g_acc1 [NN * KK];              // layer1 buckets (c_in=1)
__device__ __align__(16) float          g_acc2 [NN * KK * 32];         // layer2 buckets
__device__ __align__(16) float          g_acc3 [(size_t)NN * KK * 64]; // layer3 buckets
__device__ __align__(16) float          g_h1   [NN * 32];
__device__ __align__(16) float          g_h2   [NN * 64];
// packed hi/lo bf16 weights, B^T layout: [N, KA+KH] uints (hi in low16, lo in high16)
__device__ __align__(16) unsigned       g_Bs2  [64  * (1536 + 32)];
__device__ __align__(16) unsigned       g_Bs3  [128 * (3072 + 64)];

// ---------------- helpers ----------------
__device__ __forceinline__ uint32_t smem_u32(const void* p) {
    uint32_t a;
    asm("{ .reg .u64 t; cvta.to.shared.u64 t, %1; cvt.u32.u64 %0, t; }" : "=r"(a) : "l"(p));
    return a;
}
__device__ __forceinline__ void red_add_v4(float* p, float a, float b, float c, float d) {
    asm volatile("red.global.add.v4.f32 [%0], {%1,%2,%3,%4};"
                 :: "l"(p), "f"(a), "f"(b), "f"(c), "f"(d) : "memory");
}
__device__ __forceinline__ unsigned pack2(float v) {   // (hi bf16 low16) | (lo bf16 high16)
    __nv_bfloat16 h = __float2bfloat16(v);
    __nv_bfloat16 l = __float2bfloat16(v - __bfloat162float(h));
    union { __nv_bfloat162 b; unsigned u; } c;
    c.b = __halves2bfloat162(h, l);
    return c.u;
}
__device__ __forceinline__ unsigned bf2(float x, float y) {
    __nv_bfloat162 v = __floats2bfloat162_rn(x, y);
    union { __nv_bfloat162 b; unsigned u; } c; c.b = v; return c.u;
}
__device__ __forceinline__ float bfres(float x) {
    return x - __bfloat162float(__float2bfloat16(x));
}
__device__ __forceinline__ void mma16816(float* c, const unsigned* a, unsigned b0, unsigned b1) {
    asm volatile("mma.sync.aligned.m16n8k16.row.col.f32.bf16.bf16.f32 "
        "{%0,%1,%2,%3}, {%4,%5,%6,%7}, {%8,%9}, {%0,%1,%2,%3};"
        : "+f"(c[0]), "+f"(c[1]), "+f"(c[2]), "+f"(c[3])
        : "r"(a[0]), "r"(a[1]), "r"(a[2]), "r"(a[3]), "r"(b0), "r"(b1));
}
__device__ __forceinline__ void ldsm4(unsigned* r, uint32_t addr) {
    asm volatile("ldmatrix.sync.aligned.m8n8.x4.shared.b16 {%0,%1,%2,%3}, [%4];"
        : "=r"(r[0]), "=r"(r[1]), "=r"(r[2]), "=r"(r[3]) : "r"(addr));
}

// ---------------- basis / kernel-index precompute ----------------
__global__ void precompute_kernel(const float* __restrict__ pseudo, int E) {
    int e = blockIdx.x * blockDim.x + threadIdx.x;
    if (e >= E) return;
    float fr[3]; int lo[3];
    const int ksm1[3] = {2, 7, 1};
#pragma unroll
    for (int d = 0; d < 3; d++) {
        float u = pseudo[e * 3 + d] * (1.0f / 4.5f);
        u = fminf(fmaxf(u, 0.0f), 1.0f);
        float pos = u * (float)ksm1[d];
        float fl = floorf(pos);
        fr[d] = pos - fl;
        lo[d] = (int)fl;
    }
    float b[8]; unsigned char kx[8];
#pragma unroll
    for (int s = 0; s < 8; s++) {
        float w = 1.0f; int idx[3];
#pragma unroll
        for (int d = 0; d < 3; d++) {
            int bit = (s >> d) & 1;
            int id = lo[d] + bit;
            if (id > ksm1[d]) id = ksm1[d];
            idx[d] = id;
            w *= bit ? fr[d] : (1.0f - fr[d]);
        }
        b[s] = w;
        kx[s] = (unsigned char)(idx[0] * 16 + idx[1] * 2 + idx[2]);
    }
    *(float4*)&g_basis[e * 8]     = make_float4(b[0], b[1], b[2], b[3]);
    *(float4*)&g_basis[e * 8 + 4] = make_float4(b[4], b[5], b[6], b[7]);
    uchar4* kp = (uchar4*)&g_kidx[e * 8];
    kp[0] = make_uchar4(kx[0], kx[1], kx[2], kx[3]);
    kp[1] = make_uchar4(kx[4], kx[5], kx[6], kx[7]);
}

// ---------------- weight transpose + hi/lo split ----------------
template <int KA, int KH, int NC>
__global__ void bsplit_kernel(const float* __restrict__ W, const float* __restrict__ R) {
    constexpr int KT = KA + KH;
    unsigned* Bs = (KA == 1536) ? g_Bs2 : g_Bs3;
    int i = blockIdx.x * blockDim.x + threadIdx.x;
    if (i >= NC * KT) return;
    int n = i / KT, k = i % KT;
    float v = (k < KA) ? W[(size_t)k * NC + n] : R[(size_t)(k - KA) * NC + n];
    Bs[(size_t)n * KT + k] = pack2(v);
}

// ---------------- zero accumulators ----------------
__global__ void zero_all_kernel() {
    size_t i = (size_t)blockIdx.x * blockDim.x + threadIdx.x;
    size_t stride = (size_t)gridDim.x * blockDim.x;
    float4 z = make_float4(0.f, 0.f, 0.f, 0.f);
    for (size_t j = i; j < (size_t)(NN * KK) / 4; j += stride)      ((float4*)g_acc1)[j] = z;
    for (size_t j = i; j < (size_t)NN * KK * 32 / 4; j += stride)   ((float4*)g_acc2)[j] = z;
    for (size_t j = i; j < (size_t)NN * KK * 64 / 4; j += stride)   ((float4*)g_acc3)[j] = z;
}

// ---------------- layer-1 scatter (c_in = 1) ----------------
__global__ void scatter1_kernel(const int* __restrict__ ei, const float* __restrict__ x, int E) {
    int e = blockIdx.x * blockDim.x + threadIdx.x;
    if (e >= E) return;
    int src = ei[e], dst = ei[E + e];
    float xs = __ldg(&x[src]);
    float4 b0 = *(const float4*)&g_basis[e * 8];
    float4 b1 = *(const float4*)&g_basis[e * 8 + 4];
    uchar4 k0 = ((const uchar4*)&g_kidx[e * 8])[0];
    uchar4 k1 = ((const uchar4*)&g_kidx[e * 8])[1];
    float* base = &g_acc1[dst * KK];
    atomicAdd(base + k0.x, b0.x * xs);
    atomicAdd(base + k0.y, b0.y * xs);
    atomicAdd(base + k0.z, b0.z * xs);
    atomicAdd(base + k0.w, b0.w * xs);
    atomicAdd(base + k1.x, b1.x * xs);
    atomicAdd(base + k1.y, b1.y * xs);
    atomicAdd(base + k1.z, b1.z * xs);
    atomicAdd(base + k1.w, b1.w * xs);
}

// ---------------- layer-1 dense: h1 = relu(acc1 @ W1 + x*root1 + b1) ----------------
__global__ void dense1_kernel(const float* __restrict__ x, const float* __restrict__ W1,
                              const float* __restrict__ root1, const float* __restrict__ b1, int N) {
    int gid = blockIdx.x * blockDim.x + threadIdx.x;
    int n = gid >> 5, o = gid & 31;
    if (n >= N) return;
    float s = x[n] * root1[o] + b1[o];
    const float* a = &g_acc1[n * KK];
#pragma unroll
    for (int k = 0; k < KK; k++) s += a[k] * W1[k * 32 + o];
    g_h1[n * 32 + o] = fmaxf(s, 0.0f);
}

// ---------------- scatter for layers 2/3: acc[dst,k,:] += basis * h[src,:] ----------------
template <int CIN>
__global__ void scatter_kernel(const int* __restrict__ ei, int E) {
    int e = blockIdx.x * blockDim.x + threadIdx.x;
    if (e >= E) return;
    const float* h = (CIN == 32) ? g_h1 : g_h2;
    float* acc = (CIN == 32) ? g_acc2 : g_acc3;
    int src = ei[e], dst = ei[E + e];
    float4 hv[CIN / 4];
    const float4* hp = (const float4*)&h[(size_t)src * CIN];
#pragma unroll
    for (int i = 0; i < CIN / 4; i++) hv[i] = hp[i];
    float4 b0 = *(const float4*)&g_basis[e * 8];
    float4 b1 = *(const float4*)&g_basis[e * 8 + 4];
    float bs[8] = {b0.x, b0.y, b0.z, b0.w, b1.x, b1.y, b1.z, b1.w};
    uchar4 k0 = ((const uchar4*)&g_kidx[e * 8])[0];
    uchar4 k1 = ((const uchar4*)&g_kidx[e * 8])[1];
    int kx[8] = {k0.x, k0.y, k0.z, k0.w, k1.x, k1.y, k1.z, k1.w};
#pragma unroll
    for (int s = 0; s < 8; s++) {
        float w = bs[s];
        float* base = acc + ((size_t)dst * KK + kx[s]) * CIN;
#pragma unroll
        for (int i = 0; i < CIN / 4; i++)
            red_add_v4(base + i * 4, w * hv[i].x, w * hv[i].y, w * hv[i].z, w * hv[i].w);
    }
}

// ---------------- mma.sync bf16-split GEMM: C = relu([A|H] @ B^T + bias) ----------------
// A: [M, KA] fp32 (device symbol), H: [M, KH] fp32, Bs: [BN, KA+KH] packed hi/lo uints.
// CTA tile: 128 x BN.  K chunk = 32 fp32.  C = Ah*Bh + Ah*Bl + Al*Bh (Al*Bl dropped).
template <int KA, int KH, int BN>
__global__ void __launch_bounds__(256, 1) gemm_mma_kernel(const float* __restrict__ bias,
                                                          float* __restrict__ Cout, int M) {
    constexpr int KT = KA + KH;
    constexpr int CHA = KA / 32;
    constexpr int CHUNKS = KT / 32;
    constexpr int WN = BN / 2;           // cols per warp (4 m-warps x 2 n-warps)
    constexpr int NT8 = WN / 8;          // n8 tiles per warp
    constexpr int BJ = BN * 8 / 256;     // uint4 B loads per thread per chunk

    const float* A = (KA == 1536) ? g_acc2 : g_acc3;
    const float* H = (KA == 1536) ? g_h1 : g_h2;
    const unsigned* Bsg = (KA == 1536) ? g_Bs2 : g_Bs3;
    float* C = (KA == 1536) ? g_h2 : Cout;

    // dynamic smem: per stage: Ah 8KB | Al 8KB | Bh BN*64 | Bl BN*64
    constexpr int OFF_AL = 8192;
    constexpr int OFF_BH = 16384;
    constexpr int OFF_BL = 16384 + BN * 64;
    constexpr int STAGE  = 16384 + BN * 128;
    extern __shared__ __align__(16) char dsm[];
    const uint32_t sbase = smem_u32(dsm);

    const int t = threadIdx.x;
    const int wid = t >> 5, lane = t & 31;
    const int wm = wid & 3, wn = wid >> 2;
    const int m0 = blockIdx.x * 128;

    float4 va[4];
    uint4  vb[BJ];

    auto load_chunk = [&](int c) {
        const float* Ap = (c < CHA) ? A : H;
        const int lda = (c < CHA) ? KA : KH;
        const int k0 = (c < CHA) ? c * 32 : (c - CHA) * 32;
#pragma unroll
        for (int j = 0; j < 4; j++) {
            int slot = j * 256 + t;
            int row = slot >> 3, c4 = slot & 7;
            int gr = m0 + row;
            va[j] = (gr < M) ? *(const float4*)(Ap + (size_t)gr * lda + k0 + c4 * 4)
                             : make_float4(0.f, 0.f, 0.f, 0.f);
        }
#pragma unroll
        for (int j = 0; j < BJ; j++) {
            int slot = j * 256 + t;
            int row = slot >> 3, c4 = slot & 7;
            vb[j] = *(const uint4*)(Bsg + (size_t)row * KT + c * 32 + c4 * 4);
        }
    };
    auto store_chunk = [&](int buf) {
        char* sp = dsm + buf * STAGE;
#pragma unroll
        for (int j = 0; j < 4; j++) {
            int slot = j * 256 + t;
            int row = slot >> 3, c4 = slot & 7;
            float4 v = va[j];
            uint2 hi = make_uint2(bf2(v.x, v.y), bf2(v.z, v.w));
            uint2 lo = make_uint2(bf2(bfres(v.x), bfres(v.y)), bf2(bfres(v.z), bfres(v.w)));
            *(uint2*)(sp + row * 64 + c4 * 8) = hi;
            *(uint2*)(sp + OFF_AL + row * 64 + c4 * 8) = lo;
        }
#pragma unroll
        for (int j = 0; j < BJ; j++) {
            int slot = j * 256 + t;
            int row = slot >> 3, c4 = slot & 7;
            uint4 v = vb[j];
            uint2 hi = make_uint2((v.x & 0xffffu) | (v.y << 16), (v.z & 0xffffu) | (v.w << 16));
            uint2 lo = make_uint2((v.x >> 16) | (v.y & 0xffff0000u), (v.z >> 16) | (v.w & 0xffff0000u));
            *(uint2*)(sp + OFF_BH + row * 64 + c4 * 8) = hi;
            *(uint2*)(sp + OFF_BL + row * 64 + c4 * 8) = lo;
        }
    };

    float cacc[2][NT8][4];
#pragma unroll
    for (int i = 0; i < 2; i++)
#pragma unroll
        for (int j = 0; j < NT8; j++)
#pragma unroll
            for (int q = 0; q < 4; q++) cacc[i][j][q] = 0.0f;

    load_chunk(0);
    for (int c = 0; c < CHUNKS; c++) {
        int buf = c & 1;
        store_chunk(buf);
        __syncthreads();
        if (c + 1 < CHUNKS) load_chunk(c + 1);

        uint32_t sa = sbase + buf * STAGE;
        // ldmatrix lane address components
        int lrow = lane & 15, lkc = (lane >> 4) * 8;
#pragma unroll
        for (int ks = 0; ks < 2; ks++) {
            int kb = ks * 16;
            unsigned ah[2][4], al[2][4];
#pragma unroll
            for (int mt = 0; mt < 2; mt++) {
                uint32_t ra = (uint32_t)((wm * 32 + mt * 16 + lrow) * 64 + (kb + lkc) * 2);
                ldsm4(ah[mt], sa + ra);
                ldsm4(al[mt], sa + OFF_AL + ra);
            }
#pragma unroll
            for (int nt = 0; nt < NT8 / 2; nt++) {
                unsigned bh[4], bl[4];
                uint32_t rb = (uint32_t)((wn * WN + nt * 16 + lrow) * 64 + (kb + lkc) * 2);
                ldsm4(bh, sa + OFF_BH + rb);
                ldsm4(bl, sa + OFF_BL + rb);
#pragma unroll
                for (int mt = 0; mt < 2; mt++) {
#pragma unroll
                    for (int ns = 0; ns < 2; ns++) {
                        float* cf = cacc[mt][nt * 2 + ns];
                        mma16816(cf, ah[mt], bh[ns], bh[ns + 2]);
                        mma16816(cf, ah[mt], bl[ns], bl[ns + 2]);
                        mma16816(cf, al[mt], bh[ns], bh[ns + 2]);
                    }
                }
            }
        }
        __syncthreads();
    }

    // epilogue
#pragma unroll
    for (int mt = 0; mt < 2; mt++) {
#pragma unroll
        for (int j = 0; j < NT8; j++) {
            int row = m0 + wm * 32 + mt * 16 + (lane >> 2);
            int col = wn * WN + j * 8 + (lane & 3) * 2;
            float bx = __ldg(&bias[col]), by = __ldg(&bias[col + 1]);
            if (row < M) {
                float2 o0;
                o0.x = fmaxf(cacc[mt][j][0] + bx, 0.0f);
                o0.y = fmaxf(cacc[mt][j][1] + by, 0.0f);
                *(float2*)(C + (size_t)row * BN + col) = o0;
            }
            if (row + 8 < M) {
                float2 o1;
                o1.x = fmaxf(cacc[mt][j][2] + bx, 0.0f);
                o1.y = fmaxf(cacc[mt][j][3] + by, 0.0f);
                *(float2*)(C + (size_t)(row + 8) * BN + col) = o1;
            }
        }
    }
}

// ---------------- in-place log_softmax over 128 cols ----------------
__global__ void lsm_kernel(float* __restrict__ out) {
    int n = blockIdx.x;
    int t = threadIdx.x;
    float v = out[n * 128 + t];
    float m = v;
#pragma unroll
    for (int o = 16; o > 0; o >>= 1) m = fmaxf(m, __shfl_xor_sync(0xffffffffu, m, o));
    __shared__ float sred[4];
    __shared__ float ssum[4];
    int w = t >> 5, l = t & 31;
    if (l == 0) sred[w] = m;
    __syncthreads();
    float M4 = fmaxf(fmaxf(sred[0], sred[1]), fmaxf(sred[2], sred[3]));
    float e = expf(v - M4);
    float s = e;
#pragma unroll
    for (int o = 16; o > 0; o >>= 1) s += __shfl_xor_sync(0xffffffffu, s, o);
    if (l == 0) ssum[w] = s;
    __syncthreads();
    float S = ssum[0] + ssum[1] + ssum[2] + ssum[3];
    out[n * 128 + t] = v - M4 - logf(S);
}

// ---------------- entry ----------------
extern "C" void kernel_launch(void* const* d_in, const int* in_sizes, int n_in,
                              void* d_out, int out_size) {
    const float* x      = (const float*)d_in[0];
    const int*   ei     = (const int*)  d_in[1];
    const float* pseudo = (const float*)d_in[2];
    const float* W1     = (const float*)d_in[3];
    const float* root1  = (const float*)d_in[4];
    const float* b1     = (const float*)d_in[5];
    const float* W2     = (const float*)d_in[6];
    const float* root2  = (const float*)d_in[7];
    const float* b2     = (const float*)d_in[8];
    const float* W3     = (const float*)d_in[9];
    const float* root3  = (const float*)d_in[10];
    const float* b3     = (const float*)d_in[11];
    float* out = (float*)d_out;
    int N = in_sizes[0];
    int E = in_sizes[1] / 2;

    const int SMEM2 = 2 * (16384 + 64 * 128);    // 49152
    const int SMEM3 = 2 * (16384 + 128 * 128);   // 65536
    cudaFuncSetAttribute(gemm_mma_kernel<1536, 32, 64>,
                         cudaFuncAttributeMaxDynamicSharedMemorySize, SMEM2);
    cudaFuncSetAttribute(gemm_mma_kernel<3072, 64, 128>,
                         cudaFuncAttributeMaxDynamicSharedMemorySize, SMEM3);

    int eb = (E + 255) / 256;
    precompute_kernel<<<eb, 256>>>(pseudo, E);
    zero_all_kernel<<<4096, 256>>>();
    bsplit_kernel<1536, 32, 64><<<(64 * 1568 + 255) / 256, 256>>>(W2, root2);
    bsplit_kernel<3072, 64, 128><<<(128 * 3136 + 255) / 256, 256>>>(W3, root3);
    scatter1_kernel<<<eb, 256>>>(ei, x, E);
    dense1_kernel<<<(N * 32 + 255) / 256, 256>>>(x, W1, root1, b1, N);
    scatter_kernel<32><<<(E + 127) / 128, 128>>>(ei, E);
    gemm_mma_kernel<1536, 32, 64><<<(N + 127) / 128, 256, SMEM2>>>(b2, nullptr, N);
    scatter_kernel<64><<<(E + 127) / 128, 128>>>(ei, E);
    gemm_mma_kernel<3072, 64, 128><<<(N + 127) / 128, 256, SMEM3>>>(b3, out, N);
    lsm_kernel<<<N, 128>>>(out);
}

// round 4
// speedup vs baseline: 1.8094x; 1.6395x over previous
#include <cuda_runtime.h>
#include <cuda_bf16.h>
#include <cstdint>

#define NN 20000
#define EE 500000
#define KK 48

// ---------------- device scratch (no allocations allowed) ----------------
__device__ __align__(16) float          g_basis [EE * 8];
__device__ __align__(16) unsigned char  g_kidx  [EE * 8];
__device__ __align__(16) float          g_basis_s[EE * 8];   // sorted by dst
__device__ __align__(16) unsigned char  g_kidx_s [EE * 8];   // sorted by dst
__device__ __align__(16) int            g_src_s [EE];        // sorted src ids
__device__ __align__(16) int            g_cnt   [NN];        // per-dst degree
__device__ __align__(16) int            g_ofs   [NN + 1];    // CSR offsets
__device__ __align__(16) int            g_pos   [NN];        // running cursors
__device__ __align__(16) float          g_acc1  [NN * KK];   // layer1 buckets (c_in=1)
__device__ __align__(16) unsigned       g_acc2p [NN * KK * 32];            // packed hi/lo
__device__ __align__(16) unsigned       g_acc3p [(size_t)NN * KK * 64];    // packed hi/lo
__device__ __align__(16) float          g_h1    [NN * 32];
__device__ __align__(16) float          g_h2    [NN * 64];
// packed hi/lo bf16 weights, B^T layout: [N, KA+KH] uints (hi low16, lo high16)
__device__ __align__(16) unsigned       g_Bs2   [64  * (1536 + 32)];
__device__ __align__(16) unsigned       g_Bs3   [128 * (3072 + 64)];

// ---------------- helpers ----------------
__device__ __forceinline__ uint32_t smem_u32(const void* p) {
    uint32_t a;
    asm("{ .reg .u64 t; cvta.to.shared.u64 t, %1; cvt.u32.u64 %0, t; }" : "=r"(a) : "l"(p));
    return a;
}
__device__ __forceinline__ unsigned pack2(float v) {   // (hi bf16 low16) | (lo bf16 high16)
    __nv_bfloat16 h = __float2bfloat16(v);
    __nv_bfloat16 l = __float2bfloat16(v - __bfloat162float(h));
    union { __nv_bfloat162 b; unsigned u; } c;
    c.b = __halves2bfloat162(h, l);
    return c.u;
}
__device__ __forceinline__ unsigned bf2(float x, float y) {
    __nv_bfloat162 v = __floats2bfloat162_rn(x, y);
    union { __nv_bfloat162 b; unsigned u; } c; c.b = v; return c.u;
}
__device__ __forceinline__ float bfres(float x) {
    return x - __bfloat162float(__float2bfloat16(x));
}
__device__ __forceinline__ void mma16816(float* c, const unsigned* a, unsigned b0, unsigned b1) {
    asm volatile("mma.sync.aligned.m16n8k16.row.col.f32.bf16.bf16.f32 "
        "{%0,%1,%2,%3}, {%4,%5,%6,%7}, {%8,%9}, {%0,%1,%2,%3};"
        : "+f"(c[0]), "+f"(c[1]), "+f"(c[2]), "+f"(c[3])
        : "r"(a[0]), "r"(a[1]), "r"(a[2]), "r"(a[3]), "r"(b0), "r"(b1));
}
__device__ __forceinline__ void ldsm4(unsigned* r, uint32_t addr) {
    asm volatile("ldmatrix.sync.aligned.m8n8.x4.shared.b16 {%0,%1,%2,%3}, [%4];"
        : "=r"(r[0]), "=r"(r[1]), "=r"(r[2]), "=r"(r[3]) : "r"(addr));
}

// ---------------- basis / kernel-index precompute ----------------
__global__ void precompute_kernel(const float* __restrict__ pseudo, int E) {
    int e = blockIdx.x * blockDim.x + threadIdx.x;
    if (e >= E) return;
    float fr[3]; int lo[3];
    const int ksm1[3] = {2, 7, 1};
#pragma unroll
    for (int d = 0; d < 3; d++) {
        float u = pseudo[e * 3 + d] * (1.0f / 4.5f);
        u = fminf(fmaxf(u, 0.0f), 1.0f);
        float pos = u * (float)ksm1[d];
        float fl = floorf(pos);
        fr[d] = pos - fl;
        lo[d] = (int)fl;
    }
    float b[8]; unsigned char kx[8];
#pragma unroll
    for (int s = 0; s < 8; s++) {
        float w = 1.0f; int idx[3];
#pragma unroll
        for (int d = 0; d < 3; d++) {
            int bit = (s >> d) & 1;
            int id = lo[d] + bit;
            if (id > ksm1[d]) id = ksm1[d];
            idx[d] = id;
            w *= bit ? fr[d] : (1.0f - fr[d]);
        }
        b[s] = w;
        kx[s] = (unsigned char)(idx[0] * 16 + idx[1] * 2 + idx[2]);
    }
    *(float4*)&g_basis[e * 8]     = make_float4(b[0], b[1], b[2], b[3]);
    *(float4*)&g_basis[e * 8 + 4] = make_float4(b[4], b[5], b[6], b[7]);
    uchar4* kp = (uchar4*)&g_kidx[e * 8];
    kp[0] = make_uchar4(kx[0], kx[1], kx[2], kx[3]);
    kp[1] = make_uchar4(kx[4], kx[5], kx[6], kx[7]);
}

// ---------------- counting sort by dst ----------------
__global__ void zero_small_kernel() {
    int i = blockIdx.x * blockDim.x + threadIdx.x;
    if (i < NN) g_cnt[i] = 0;
    if (i < NN * KK) g_acc1[i] = 0.0f;
}
__global__ void hist_kernel(const int* __restrict__ ei, int E) {
    int e = blockIdx.x * blockDim.x + threadIdx.x;
    if (e < E) atomicAdd(&g_cnt[ei[E + e]], 1);
}
__global__ void prefix_kernel() {
    __shared__ int warp_sums[32];
    __shared__ int s_carry;
    int t = threadIdx.x;
    if (t == 0) s_carry = 0;
    __syncthreads();
    for (int base = 0; base < NN; base += 1024) {
        int v = (base + t < NN) ? g_cnt[base + t] : 0;
        int x = v;
#pragma unroll
        for (int o = 1; o < 32; o <<= 1) {
            int y = __shfl_up_sync(~0u, x, o);
            if ((t & 31) >= o) x += y;
        }
        if ((t & 31) == 31) warp_sums[t >> 5] = x;
        __syncthreads();
        if (t < 32) {
            int w = warp_sums[t];
#pragma unroll
            for (int o = 1; o < 32; o <<= 1) {
                int y = __shfl_up_sync(~0u, w, o);
                if (t >= o) w += y;
            }
            warp_sums[t] = w;
        }
        __syncthreads();
        int incl = x + ((t >= 32) ? warp_sums[(t >> 5) - 1] : 0);
        int total = warp_sums[31];
        int excl = s_carry + incl - v;
        if (base + t < NN) { g_ofs[base + t] = excl; g_pos[base + t] = excl; }
        __syncthreads();
        if (t == 0) s_carry += total;
        __syncthreads();
    }
    if (t == 0) g_ofs[NN] = EE;
}
__global__ void order_kernel(const int* __restrict__ ei, int E) {
    int e = blockIdx.x * blockDim.x + threadIdx.x;
    if (e >= E) return;
    int dst = ei[E + e];
    int p = atomicAdd(&g_pos[dst], 1);
    g_src_s[p] = ei[e];
    float4 b0 = *(const float4*)&g_basis[e * 8];
    float4 b1 = *(const float4*)&g_basis[e * 8 + 4];
    *(float4*)&g_basis_s[p * 8]     = b0;
    *(float4*)&g_basis_s[p * 8 + 4] = b1;
    uint2 kv = *(const uint2*)&g_kidx[e * 8];
    *(uint2*)&g_kidx_s[p * 8] = kv;
}

// ---------------- weight transpose + hi/lo split ----------------
template <int KA, int KH, int NC>
__global__ void bsplit_kernel(const float* __restrict__ W, const float* __restrict__ R) {
    constexpr int KT = KA + KH;
    unsigned* Bs = (KA == 1536) ? g_Bs2 : g_Bs3;
    int i = blockIdx.x * blockDim.x + threadIdx.x;
    if (i >= NC * KT) return;
    int n = i / KT, k = i % KT;
    float v = (k < KA) ? W[(size_t)k * NC + n] : R[(size_t)(k - KA) * NC + n];
    Bs[(size_t)n * KT + k] = pack2(v);
}

// ---------------- layer-1 scatter (c_in = 1, atomics into small L2 buffer) ----------------
__global__ void scatter1_kernel(const int* __restrict__ ei, const float* __restrict__ x, int E) {
    int e = blockIdx.x * blockDim.x + threadIdx.x;
    if (e >= E) return;
    int src = ei[e], dst = ei[E + e];
    float xs = __ldg(&x[src]);
    float4 b0 = *(const float4*)&g_basis[e * 8];
    float4 b1 = *(const float4*)&g_basis[e * 8 + 4];
    uchar4 k0 = ((const uchar4*)&g_kidx[e * 8])[0];
    uchar4 k1 = ((const uchar4*)&g_kidx[e * 8])[1];
    float* base = &g_acc1[dst * KK];
    atomicAdd(base + k0.x, b0.x * xs);
    atomicAdd(base + k0.y, b0.y * xs);
    atomicAdd(base + k0.z, b0.z * xs);
    atomicAdd(base + k0.w, b0.w * xs);
    atomicAdd(base + k1.x, b1.x * xs);
    atomicAdd(base + k1.y, b1.y * xs);
    atomicAdd(base + k1.z, b1.z * xs);
    atomicAdd(base + k1.w, b1.w * xs);
}

// ---------------- layer-1 dense: h1 = relu(acc1 @ W1 + x*root1 + b1) ----------------
__global__ void dense1_kernel(const float* __restrict__ x, const float* __restrict__ W1,
                              const float* __restrict__ root1, const float* __restrict__ b1, int N) {
    int gid = blockIdx.x * blockDim.x + threadIdx.x;
    int n = gid >> 5, o = gid & 31;
    if (n >= N) return;
    float s = x[n] * root1[o] + b1[o];
    const float* a = &g_acc1[n * KK];
#pragma unroll
    for (int k = 0; k < KK; k++) s += a[k] * W1[k * 32 + o];
    g_h1[n * 32 + o] = fmaxf(s, 0.0f);
}

// ---------------- per-node bucket scatter: acc[n,k,:] = sum_e basis * h[src,:] ----------------
// One CTA per node, CIN threads. Thread t exclusively owns channel t of the whole
// [KK, CIN] bucket -> no atomics, no syncs, conflict-free smem.
template <int CIN>
__global__ void __launch_bounds__(CIN) gather_scatter_kernel(int N) {
    const float* __restrict__ h = (CIN == 32) ? g_h1 : g_h2;
    unsigned* __restrict__ accP = (CIN == 32) ? g_acc2p : g_acc3p;
    __shared__ float buck[KK * CIN];
    int n = blockIdx.x;
    int t = threadIdx.x;
#pragma unroll
    for (int k = 0; k < KK; k++) buck[k * CIN + t] = 0.0f;

    int beg = g_ofs[n], end = g_ofs[n + 1];
    for (int i = beg; i < end; i++) {
        int src = g_src_s[i];
        float hv = h[(size_t)src * CIN + t];
        float4 b0 = *(const float4*)&g_basis_s[i * 8];
        float4 b1 = *(const float4*)&g_basis_s[i * 8 + 4];
        uchar4 k0 = ((const uchar4*)&g_kidx_s[i * 8])[0];
        uchar4 k1 = ((const uchar4*)&g_kidx_s[i * 8])[1];
        buck[k0.x * CIN + t] += b0.x * hv;
        buck[k0.y * CIN + t] += b0.y * hv;
        buck[k0.z * CIN + t] += b0.z * hv;
        buck[k0.w * CIN + t] += b0.w * hv;
        buck[k1.x * CIN + t] += b1.x * hv;
        buck[k1.y * CIN + t] += b1.y * hv;
        buck[k1.z * CIN + t] += b1.z * hv;
        buck[k1.w * CIN + t] += b1.w * hv;
    }
    unsigned* out = accP + (size_t)n * KK * CIN + t;
#pragma unroll
    for (int k = 0; k < KK; k++) out[k * CIN] = pack2(buck[k * CIN + t]);
}

// ---------------- mma.sync bf16-split GEMM: C = relu([A|H] @ B^T + bias) ----------------
// A: [M, KA] packed hi/lo uints, H: [M, KH] fp32, Bs: [BN, KA+KH] packed uints.
// CTA tile: 128 x BN.  K chunk = 32 values.  C = Ah*Bh + Ah*Bl + Al*Bh (Al*Bl dropped).
template <int KA, int KH, int BN>
__global__ void __launch_bounds__(256, 1) gemm_mma_kernel(const float* __restrict__ bias,
                                                          float* __restrict__ Cout, int M) {
    constexpr int KT = KA + KH;
    constexpr int CHA = KA / 32;
    constexpr int CHUNKS = KT / 32;
    constexpr int WN = BN / 2;
    constexpr int NT8 = WN / 8;
    constexpr int BJ = BN * 8 / 256;

    const unsigned* A = (KA == 1536) ? g_acc2p : g_acc3p;
    const float* H = (KA == 1536) ? g_h1 : g_h2;
    const unsigned* Bsg = (KA == 1536) ? g_Bs2 : g_Bs3;
    float* C = (KA == 1536) ? g_h2 : Cout;

    constexpr int OFF_AL = 8192;
    constexpr int OFF_BH = 16384;
    constexpr int OFF_BL = 16384 + BN * 64;
    constexpr int STAGE  = 16384 + BN * 128;
    extern __shared__ __align__(16) char dsm[];
    const uint32_t sbase = smem_u32(dsm);

    const int t = threadIdx.x;
    const int wid = t >> 5, lane = t & 31;
    const int wm = wid & 3, wn = wid >> 2;
    const int m0 = blockIdx.x * 128;

    union { uint4 u; float4 f; } va[4];
    uint4 vb[BJ];

    auto load_chunk = [&](int c) {
        if (c < CHA) {
            int k0 = c * 32;
#pragma unroll
            for (int j = 0; j < 4; j++) {
                int slot = j * 256 + t;
                int row = slot >> 3, c4 = slot & 7;
                int gr = m0 + row;
                va[j].u = (gr < M) ? *(const uint4*)(A + (size_t)gr * KA + k0 + c4 * 4)
                                   : make_uint4(0u, 0u, 0u, 0u);
            }
        } else {
            int k0 = (c - CHA) * 32;
#pragma unroll
            for (int j = 0; j < 4; j++) {
                int slot = j * 256 + t;
                int row = slot >> 3, c4 = slot & 7;
                int gr = m0 + row;
                va[j].f = (gr < M) ? *(const float4*)(H + (size_t)gr * KH + k0 + c4 * 4)
                                   : make_float4(0.f, 0.f, 0.f, 0.f);
            }
        }
#pragma unroll
        for (int j = 0; j < BJ; j++) {
            int slot = j * 256 + t;
            int row = slot >> 3, c4 = slot & 7;
            vb[j] = *(const uint4*)(Bsg + (size_t)row * KT + c * 32 + c4 * 4);
        }
    };
    auto store_chunk = [&](int buf, int c) {
        char* sp = dsm + buf * STAGE;
#pragma unroll
        for (int j = 0; j < 4; j++) {
            int slot = j * 256 + t;
            int row = slot >> 3, c4 = slot & 7;
            uint2 hi, lo;
            if (c < CHA) {
                uint4 v = va[j].u;
                hi = make_uint2((v.x & 0xffffu) | (v.y << 16), (v.z & 0xffffu) | (v.w << 16));
                lo = make_uint2((v.x >> 16) | (v.y & 0xffff0000u), (v.z >> 16) | (v.w & 0xffff0000u));
            } else {
                float4 v = va[j].f;
                hi = make_uint2(bf2(v.x, v.y), bf2(v.z, v.w));
                lo = make_uint2(bf2(bfres(v.x), bfres(v.y)), bf2(bfres(v.z), bfres(v.w)));
            }
            *(uint2*)(sp + row * 64 + c4 * 8) = hi;
            *(uint2*)(sp + OFF_AL + row * 64 + c4 * 8) = lo;
        }
#pragma unroll
        for (int j = 0; j < BJ; j++) {
            int slot = j * 256 + t;
            int row = slot >> 3, c4 = slot & 7;
            uint4 v = vb[j];
            uint2 hi = make_uint2((v.x & 0xffffu) | (v.y << 16), (v.z & 0xffffu) | (v.w << 16));
            uint2 lo = make_uint2((v.x >> 16) | (v.y & 0xffff0000u), (v.z >> 16) | (v.w & 0xffff0000u));
            *(uint2*)(sp + OFF_BH + row * 64 + c4 * 8) = hi;
            *(uint2*)(sp + OFF_BL + row * 64 + c4 * 8) = lo;
        }
    };

    float cacc[2][NT8][4];
#pragma unroll
    for (int i = 0; i < 2; i++)
#pragma unroll
        for (int j = 0; j < NT8; j++)
#pragma unroll
            for (int q = 0; q < 4; q++) cacc[i][j][q] = 0.0f;

    load_chunk(0);
    for (int c = 0; c < CHUNKS; c++) {
        int buf = c & 1;
        store_chunk(buf, c);
        __syncthreads();
        if (c + 1 < CHUNKS) load_chunk(c + 1);

        uint32_t sa = sbase + buf * STAGE;
        int lrow = lane & 15, lkc = (lane >> 4) * 8;
#pragma unroll
        for (int ks = 0; ks < 2; ks++) {
            int kb = ks * 16;
            unsigned ah[2][4], al[2][4];
#pragma unroll
            for (int mt = 0; mt < 2; mt++) {
                uint32_t ra = (uint32_t)((wm * 32 + mt * 16 + lrow) * 64 + (kb + lkc) * 2);
                ldsm4(ah[mt], sa + ra);
                ldsm4(al[mt], sa + OFF_AL + ra);
            }
#pragma unroll
            for (int nt = 0; nt < NT8 / 2; nt++) {
                unsigned bh[4], bl[4];
                uint32_t rb = (uint32_t)((wn * WN + nt * 16 + lrow) * 64 + (kb + lkc) * 2);
                ldsm4(bh, sa + OFF_BH + rb);
                ldsm4(bl, sa + OFF_BL + rb);
#pragma unroll
                for (int mt = 0; mt < 2; mt++) {
#pragma unroll
                    for (int ns = 0; ns < 2; ns++) {
                        float* cf = cacc[mt][nt * 2 + ns];
                        mma16816(cf, ah[mt], bh[ns], bh[ns + 2]);
                        mma16816(cf, ah[mt], bl[ns], bl[ns + 2]);
                        mma16816(cf, al[mt], bh[ns], bh[ns + 2]);
                    }
                }
            }
        }
        __syncthreads();
    }

#pragma unroll
    for (int mt = 0; mt < 2; mt++) {
#pragma unroll
        for (int j = 0; j < NT8; j++) {
            int row = m0 + wm * 32 + mt * 16 + (lane >> 2);
            int col = wn * WN + j * 8 + (lane & 3) * 2;
            float bx = __ldg(&bias[col]), by = __ldg(&bias[col + 1]);
            if (row < M) {
                float2 o0;
                o0.x = fmaxf(cacc[mt][j][0] + bx, 0.0f);
                o0.y = fmaxf(cacc[mt][j][1] + by, 0.0f);
                *(float2*)(C + (size_t)row * BN + col) = o0;
            }
            if (row + 8 < M) {
                float2 o1;
                o1.x = fmaxf(cacc[mt][j][2] + bx, 0.0f);
                o1.y = fmaxf(cacc[mt][j][3] + by, 0.0f);
                *(float2*)(C + (size_t)(row + 8) * BN + col) = o1;
            }
        }
    }
}

// ---------------- in-place log_softmax over 128 cols ----------------
__global__ void lsm_kernel(float* __restrict__ out) {
    int n = blockIdx.x;
    int t = threadIdx.x;
    float v = out[n * 128 + t];
    float m = v;
#pragma unroll
    for (int o = 16; o > 0; o >>= 1) m = fmaxf(m, __shfl_xor_sync(0xffffffffu, m, o));
    __shared__ float sred[4];
    __shared__ float ssum[4];
    int w = t >> 5, l = t & 31;
    if (l == 0) sred[w] = m;
    __syncthreads();
    float M4 = fmaxf(fmaxf(sred[0], sred[1]), fmaxf(sred[2], sred[3]));
    float e = expf(v - M4);
    float s = e;
#pragma unroll
    for (int o = 16; o > 0; o >>= 1) s += __shfl_xor_sync(0xffffffffu, s, o);
    if (l == 0) ssum[w] = s;
    __syncthreads();
    float S = ssum[0] + ssum[1] + ssum[2] + ssum[3];
    out[n * 128 + t] = v - M4 - logf(S);
}

// ---------------- entry ----------------
extern "C" void kernel_launch(void* const* d_in, const int* in_sizes, int n_in,
                              void* d_out, int out_size) {
    const float* x      = (const float*)d_in[0];
    const int*   ei     = (const int*)  d_in[1];
    const float* pseudo = (const float*)d_in[2];
    const float* W1     = (const float*)d_in[3];
    const float* root1  = (const float*)d_in[4];
    const float* b1     = (const float*)d_in[5];
    const float* W2     = (const float*)d_in[6];
    const float* root2  = (const float*)d_in[7];
    const float* b2     = (const float*)d_in[8];
    const float* W3     = (const float*)d_in[9];
    const float* root3  = (const float*)d_in[10];
    const float* b3     = (const float*)d_in[11];
    float* out = (float*)d_out;
    int N = in_sizes[0];
    int E = in_sizes[1] / 2;

    const int SMEM2 = 2 * (16384 + 64 * 128);    // 49152
    const int SMEM3 = 2 * (16384 + 128 * 128);   // 65536
    cudaFuncSetAttribute(gemm_mma_kernel<1536, 32, 64>,
                         cudaFuncAttributeMaxDynamicSharedMemorySize, SMEM2);
    cudaFuncSetAttribute(gemm_mma_kernel<3072, 64, 128>,
                         cudaFuncAttributeMaxDynamicSharedMemorySize, SMEM3);

    int eb = (E + 255) / 256;
    precompute_kernel<<<eb, 256>>>(pseudo, E);
    zero_small_kernel<<<(NN * KK + 255) / 256, 256>>>();
    hist_kernel<<<eb, 256>>>(ei, E);
    prefix_kernel<<<1, 1024>>>();
    order_kernel<<<eb, 256>>>(ei, E);
    bsplit_kernel<1536, 32, 64><<<(64 * 1568 + 255) / 256, 256>>>(W2, root2);
    bsplit_kernel<3072, 64, 128><<<(128 * 3136 + 255) / 256, 256>>>(W3, root3);
    scatter1_kernel<<<eb, 256>>>(ei, x, E);
    dense1_kernel<<<(N * 32 + 255) / 256, 256>>>(x, W1, root1, b1, N);
    gather_scatter_kernel<32><<<N, 32>>>(N);
    gemm_mma_kernel<1536, 32, 64><<<(N + 127) / 128, 256, SMEM2>>>(b2, nullptr, N);
    gather_scatter_kernel<64><<<N, 64>>>(N);
    gemm_mma_kernel<3072, 64, 128><<<(N + 127) / 128, 256, SMEM3>>>(b3, out, N);
    lsm_kernel<<<N, 128>>>(out);
}

// round 8
// speedup vs baseline: 2.3995x; 1.3261x over previous
#include <cuda_runtime.h>
#include <cuda_bf16.h>
#include <cstdint>

#define NN 20000
#define EE 500000
#define KK 48

// ---------------- device scratch (no allocations allowed) ----------------
struct __align__(16) ERec { float b[8]; unsigned kx[2]; int src; int pad; };  // 48B

__device__ __align__(16) float    g_basis [EE * 8];
__device__ __align__(16) unsigned char g_kidx [EE * 8];
__device__ __align__(16) ERec     g_rec   [EE];          // dst-sorted edge records
__device__ __align__(16) int      g_cnt   [NN];
__device__ __align__(16) int      g_ofs   [NN + 1];
__device__ __align__(16) int      g_pos   [NN];
__device__ __align__(16) float    g_acc1  [NN * KK];
// block-split hi/lo bf16 planes: per row, group of 8 values = [8 hi u16][8 lo u16]
__device__ __align__(16) unsigned g_acc2p [NN * KK * 32];
__device__ __align__(16) unsigned g_acc3p [(size_t)NN * KK * 64];
__device__ __align__(16) float    g_h1    [NN * 32];
__device__ __align__(16) float    g_h2    [NN * 64];
__device__ __align__(16) unsigned g_h1s   [NN * 32];     // block-split of g_h1
__device__ __align__(16) unsigned g_h2s   [NN * 64];     // block-split of g_h2
__device__ __align__(16) unsigned g_Bs2   [64  * (1536 + 32)];   // block-split B^T
__device__ __align__(16) unsigned g_Bs3   [128 * (3072 + 64)];

// ---------------- helpers ----------------
__device__ __forceinline__ uint32_t smem_u32(const void* p) {
    uint32_t a;
    asm("{ .reg .u64 t; cvta.to.shared.u64 t, %1; cvt.u32.u64 %0, t; }" : "=r"(a) : "l"(p));
    return a;
}
__device__ __forceinline__ unsigned short bfh(float v) {
    __nv_bfloat16 h = __float2bfloat16(v);
    union { __nv_bfloat16 b; unsigned short u; } c; c.b = h; return c.u;
}
__device__ __forceinline__ float bfhf(float v) {   // value of hi part
    return __bfloat162float(__float2bfloat16(v));
}
__device__ __forceinline__ void split8(const float* v, uint4& hb, uint4& lb) {
    unsigned h[4], l[4];
#pragma unroll
    for (int i = 0; i < 4; i++) {
        float a = v[i * 2], b = v[i * 2 + 1];
        h[i] = (unsigned)bfh(a) | ((unsigned)bfh(b) << 16);
        l[i] = (unsigned)bfh(a - bfhf(a)) | ((unsigned)bfh(b - bfhf(b)) << 16);
    }
    hb = make_uint4(h[0], h[1], h[2], h[3]);
    lb = make_uint4(l[0], l[1], l[2], l[3]);
}
__device__ __forceinline__ void mma16816(float* c, const unsigned* a, unsigned b0, unsigned b1) {
    asm volatile("mma.sync.aligned.m16n8k16.row.col.f32.bf16.bf16.f32 "
        "{%0,%1,%2,%3}, {%4,%5,%6,%7}, {%8,%9}, {%0,%1,%2,%3};"
        : "+f"(c[0]), "+f"(c[1]), "+f"(c[2]), "+f"(c[3])
        : "r"(a[0]), "r"(a[1]), "r"(a[2]), "r"(a[3]), "r"(b0), "r"(b1));
}
__device__ __forceinline__ void ldsm4(unsigned* r, uint32_t addr) {
    asm volatile("ldmatrix.sync.aligned.m8n8.x4.shared.b16 {%0,%1,%2,%3}, [%4];"
        : "=r"(r[0]), "=r"(r[1]), "=r"(r[2]), "=r"(r[3]) : "r"(addr));
}
__device__ __forceinline__ void cpa16(uint32_t dst, const void* src, int sz) {
    asm volatile("cp.async.cg.shared.global [%0], [%1], 16, %2;" :: "r"(dst), "l"(src), "r"(sz));
}
__device__ __forceinline__ void cpa16f(uint32_t dst, const void* src) {
    asm volatile("cp.async.cg.shared.global [%0], [%1], 16;" :: "r"(dst), "l"(src));
}

// ---------------- basis/kidx precompute + zero-init fold ----------------
__global__ void precompute_kernel(const float* __restrict__ pseudo, int E) {
    int e = blockIdx.x * blockDim.x + threadIdx.x;
    if (e >= E) return;
    if (e < NN) g_cnt[e] = 0;
    g_acc1[e % (NN * KK)] = 0.0f;
    if (e + EE < NN * KK) g_acc1[e + EE] = 0.0f;
    float fr[3]; int lo[3];
    const int ksm1[3] = {2, 7, 1};
#pragma unroll
    for (int d = 0; d < 3; d++) {
        float u = pseudo[e * 3 + d] * (1.0f / 4.5f);
        u = fminf(fmaxf(u, 0.0f), 1.0f);
        float pos = u * (float)ksm1[d];
        float fl = floorf(pos);
        fr[d] = pos - fl;
        lo[d] = (int)fl;
    }
    float b[8]; unsigned char kx[8];
#pragma unroll
    for (int s = 0; s < 8; s++) {
        float w = 1.0f; int idx[3];
#pragma unroll
        for (int d = 0; d < 3; d++) {
            int bit = (s >> d) & 1;
            int id = lo[d] + bit;
            if (id > ksm1[d]) id = ksm1[d];
            idx[d] = id;
            w *= bit ? fr[d] : (1.0f - fr[d]);
        }
        b[s] = w;
        kx[s] = (unsigned char)(idx[0] * 16 + idx[1] * 2 + idx[2]);
    }
    *(float4*)&g_basis[e * 8]     = make_float4(b[0], b[1], b[2], b[3]);
    *(float4*)&g_basis[e * 8 + 4] = make_float4(b[4], b[5], b[6], b[7]);
    uchar4* kp = (uchar4*)&g_kidx[e * 8];
    kp[0] = make_uchar4(kx[0], kx[1], kx[2], kx[3]);
    kp[1] = make_uchar4(kx[4], kx[5], kx[6], kx[7]);
}

__global__ void hist_kernel(const int* __restrict__ ei, int E) {
    int e = blockIdx.x * blockDim.x + threadIdx.x;
    if (e < E) atomicAdd(&g_cnt[ei[E + e]], 1);
}

// fast single-block scan: each thread owns 20 contiguous elements
__global__ void prefix_kernel() {
    constexpr int PER = (NN + 1023) / 1024;   // 20
    __shared__ int ws[32];
    int t = threadIdx.x;
    int base = t * PER;
    int loc[PER]; int sum = 0;
#pragma unroll
    for (int i = 0; i < PER; i++) {
        int idx = base + i;
        int v = (idx < NN) ? g_cnt[idx] : 0;
        loc[i] = sum; sum += v;
    }
    int x = sum;
#pragma unroll
    for (int o = 1; o < 32; o <<= 1) {
        int y = __shfl_up_sync(~0u, x, o);
        if ((t & 31) >= o) x += y;
    }
    if ((t & 31) == 31) ws[t >> 5] = x;
    __syncthreads();
    if (t < 32) {
        int w = ws[t];
#pragma unroll
        for (int o = 1; o < 32; o <<= 1) {
            int y = __shfl_up_sync(~0u, w, o);
            if (t >= o) w += y;
        }
        ws[t] = w;
    }
    __syncthreads();
    int ex = x - sum + ((t >= 32) ? ws[(t >> 5) - 1] : 0);
#pragma unroll
    for (int i = 0; i < PER; i++) {
        int idx = base + i;
        if (idx < NN) { g_ofs[idx] = ex + loc[i]; g_pos[idx] = ex + loc[i]; }
    }
    if (t == 1023) g_ofs[NN] = ex + sum;
}

__global__ void order_kernel(const int* __restrict__ ei, int E) {
    int e = blockIdx.x * blockDim.x + threadIdx.x;
    if (e >= E) return;
    int dst = ei[E + e];
    int p = atomicAdd(&g_pos[dst], 1);
    uint4 q0 = *(const uint4*)&g_basis[e * 8];
    uint4 q1 = *(const uint4*)&g_basis[e * 8 + 4];
    uint2 kv = *(const uint2*)&g_kidx[e * 8];
    uint4 q2 = make_uint4(kv.x, kv.y, (unsigned)ei[e], 0u);
    uint4* rp = (uint4*)&g_rec[p];
    rp[0] = q0; rp[1] = q1; rp[2] = q2;
}

// ---------------- weight transpose + block-split (8-group hi/lo) ----------------
template <int KA, int KH, int NC>
__global__ void bsplit_kernel(const float* __restrict__ W, const float* __restrict__ R) {
    constexpr int KT = KA + KH;
    unsigned* Bs = (KA == 1536) ? g_Bs2 : g_Bs3;
    int i = blockIdx.x * blockDim.x + threadIdx.x;
    if (i >= NC * (KT / 8)) return;
    int n = i / (KT / 8), g = i % (KT / 8);
    float v[8];
#pragma unroll
    for (int j = 0; j < 8; j++) {
        int k = g * 8 + j;
        v[j] = (k < KA) ? W[(size_t)k * NC + n] : R[(size_t)(k - KA) * NC + n];
    }
    uint4 hb, lb; split8(v, hb, lb);
    char* row = (char*)(Bs + (size_t)n * KT);
    *(uint4*)(row + g * 32)      = hb;
    *(uint4*)(row + g * 32 + 16) = lb;
}

// block-split copy of an fp32 feature matrix
template <int CIN>
__global__ void hsplit_kernel(int N) {
    const float* __restrict__ h = (CIN == 32) ? g_h1 : g_h2;
    unsigned* __restrict__ hs = (CIN == 32) ? g_h1s : g_h2s;
    int i = blockIdx.x * blockDim.x + threadIdx.x;
    if (i >= N * (CIN / 8)) return;
    int n = i / (CIN / 8), g = i % (CIN / 8);
    float v[8];
    const float* src = h + (size_t)n * CIN + g * 8;
#pragma unroll
    for (int j = 0; j < 8; j++) v[j] = src[j];
    uint4 hb, lb; split8(v, hb, lb);
    char* row = (char*)(hs + (size_t)n * CIN);
    *(uint4*)(row + g * 32)      = hb;
    *(uint4*)(row + g * 32 + 16) = lb;
}

// ---------------- layer-1 scatter (c_in = 1) ----------------
__global__ void scatter1_kernel(const int* __restrict__ ei, const float* __restrict__ x, int E) {
    int e = blockIdx.x * blockDim.x + threadIdx.x;
    if (e >= E) return;
    int src = ei[e], dst = ei[E + e];
    float xs = __ldg(&x[src]);
    float4 b0 = *(const float4*)&g_basis[e * 8];
    float4 b1 = *(const float4*)&g_basis[e * 8 + 4];
    uchar4 k0 = ((const uchar4*)&g_kidx[e * 8])[0];
    uchar4 k1 = ((const uchar4*)&g_kidx[e * 8])[1];
    float* base = &g_acc1[dst * KK];
    atomicAdd(base + k0.x, b0.x * xs);
    atomicAdd(base + k0.y, b0.y * xs);
    atomicAdd(base + k0.z, b0.z * xs);
    atomicAdd(base + k0.w, b0.w * xs);
    atomicAdd(base + k1.x, b1.x * xs);
    atomicAdd(base + k1.y, b1.y * xs);
    atomicAdd(base + k1.z, b1.z * xs);
    atomicAdd(base + k1.w, b1.w * xs);
}

// ---------------- layer-1 dense ----------------
__global__ void dense1_kernel(const float* __restrict__ x, const float* __restrict__ W1,
                              const float* __restrict__ root1, const float* __restrict__ b1, int N) {
    int gid = blockIdx.x * blockDim.x + threadIdx.x;
    int n = gid >> 5, o = gid & 31;
    if (n >= N) return;
    float s = x[n] * root1[o] + b1[o];
    const float* a = &g_acc1[n * KK];
#pragma unroll
    for (int k = 0; k < KK; k++) s += a[k] * W1[k * 32 + o];
    g_h1[n * 32 + o] = fmaxf(s, 0.0f);
}

// ---------------- per-node bucket scatter -> block-split output ----------------
template <int CIN>
__global__ void __launch_bounds__(CIN) gather_scatter_kernel(int N) {
    const float* __restrict__ h = (CIN == 32) ? g_h1 : g_h2;
    unsigned* __restrict__ accP = (CIN == 32) ? g_acc2p : g_acc3p;
    __shared__ float buck[KK * CIN];
    int n = blockIdx.x;
    int t = threadIdx.x;
#pragma unroll
    for (int k = 0; k < KK; k++) buck[k * CIN + t] = 0.0f;

    int beg = g_ofs[n], end = g_ofs[n + 1];
    if (beg < end) {
        const uint4* rp = (const uint4*)&g_rec[beg];
        uint4 q0 = rp[0], q1 = rp[1], q2 = rp[2];
        float hv = h[(size_t)(int)q2.z * CIN + t];
        for (int i = beg; i < end; i++) {
            uint4 n0, n1, n2; float hvn = 0.0f;
            if (i + 1 < end) {
                const uint4* np = (const uint4*)&g_rec[i + 1];
                n0 = np[0]; n1 = np[1]; n2 = np[2];
                hvn = h[(size_t)(int)n2.z * CIN + t];
            }
            float bs[8] = {__uint_as_float(q0.x), __uint_as_float(q0.y),
                           __uint_as_float(q0.z), __uint_as_float(q0.w),
                           __uint_as_float(q1.x), __uint_as_float(q1.y),
                           __uint_as_float(q1.z), __uint_as_float(q1.w)};
            unsigned ka = q2.x, kb = q2.y;
            buck[((ka      ) & 0xff) * CIN + t] += bs[0] * hv;
            buck[((ka >>  8) & 0xff) * CIN + t] += bs[1] * hv;
            buck[((ka >> 16) & 0xff) * CIN + t] += bs[2] * hv;
            buck[((ka >> 24)       ) * CIN + t] += bs[3] * hv;
            buck[((kb      ) & 0xff) * CIN + t] += bs[4] * hv;
            buck[((kb >>  8) & 0xff) * CIN + t] += bs[5] * hv;
            buck[((kb >> 16) & 0xff) * CIN + t] += bs[6] * hv;
            buck[((kb >> 24)       ) * CIN + t] += bs[7] * hv;
            q0 = n0; q1 = n1; q2 = n2; hv = hvn;
        }
    }
    __syncthreads();
    // write block-split row: group g = 8 consecutive flat (k,ch) values
    char* row = (char*)(accP + (size_t)n * KK * CIN);
    constexpr int NG = KK * CIN / 8;
#pragma unroll
    for (int g = t; g < NG; g += CIN) {
        float v[8];
#pragma unroll
        for (int j = 0; j < 8; j++) v[j] = buck[g * 8 + j];
        uint4 hb, lb; split8(v, hb, lb);
        *(uint4*)(row + g * 32)      = hb;
        *(uint4*)(row + g * 32 + 16) = lb;
    }
}

// ---------------- cp.async bf16-split GEMM: C = relu([A|H] @ B^T + bias) ----------------
// All operands pre-split in global in block-split format; GEMM does zero conversion.
// BM=64 rows per CTA (tail-friendly grid), K chunk = 32 values = 128B/row.
template <int KA, int KH, int BN>
__global__ void __launch_bounds__(256) gemm_cp_kernel(const float* __restrict__ bias,
                                                      float* __restrict__ Cout, int M) {
    constexpr int KT = KA + KH;
    constexpr int CHA = KA / 32, CH = KT / 32;
    constexpr int BM = 64;
    constexpr int ASZ = BM * 128, BSZ = BN * 128, STAGE = ASZ + BSZ;
    constexpr int NTP = BN / 64;              // nt16 tiles per warp (wn covers BN/4 cols... )
    extern __shared__ __align__(16) char dsm[];
    const uint32_t sb = smem_u32(dsm);

    const unsigned* Ag = (KA == 1536) ? g_acc2p : g_acc3p;
    const unsigned* Hg = (KA == 1536) ? g_h1s : g_h2s;
    const unsigned* Bg = (KA == 1536) ? g_Bs2 : g_Bs3;
    float* C = (KA == 1536) ? g_h2 : Cout;

    const int t = threadIdx.x, wid = t >> 5, lane = t & 31;
    const int wm = wid & 1, wn = wid >> 1;        // 2 x 4 warps; warp tile 32 x (BN/4)
    const int m0 = blockIdx.x * BM;
    const int lr = lane & 15, lh = lane >> 4;

    auto issue = [&](int c) {
        int buf = c & 1;
        uint32_t sA = sb + buf * STAGE, sB = sA + ASZ;
        const char* gA; size_t strA;
        if (c < CHA) { gA = (const char*)Ag + (size_t)c * 128;        strA = (size_t)KA * 4; }
        else         { gA = (const char*)Hg + (size_t)(c - CHA) * 128; strA = (size_t)KH * 4; }
#pragma unroll
        for (int j = 0; j < 2; j++) {
            int slot = j * 256 + t;
            int r = slot >> 3, s = slot & 7;
            int gr = m0 + r;
            cpa16(sA + r * 128 + ((s ^ (r & 7)) * 16),
                  gA + (size_t)gr * strA + s * 16, (gr < M) ? 16 : 0);
        }
        const char* gB = (const char*)Bg + (size_t)c * 128;
#pragma unroll
        for (int j = 0; j < BN / 32; j++) {
            int slot = j * 256 + t;
            int r = slot >> 3, s = slot & 7;
            cpa16f(sB + r * 128 + ((s ^ (r & 7)) * 16),
                   gB + (size_t)r * ((size_t)KT * 4) + s * 16);
        }
        asm volatile("cp.async.commit_group;" ::: "memory");
    };

    float cacc[2][NTP * 2][4];
#pragma unroll
    for (int i = 0; i < 2; i++)
#pragma unroll
        for (int j = 0; j < NTP * 2; j++)
#pragma unroll
            for (int q = 0; q < 4; q++) cacc[i][j][q] = 0.0f;

    issue(0);
    for (int c = 0; c < CH; c++) {
        if (c + 1 < CH) {
            issue(c + 1);
            asm volatile("cp.async.wait_group 1;" ::: "memory");
        } else {
            asm volatile("cp.async.wait_group 0;" ::: "memory");
        }
        __syncthreads();

        uint32_t sA = sb + (c & 1) * STAGE, sB = sA + ASZ;
#pragma unroll
        for (int ks = 0; ks < 2; ks++) {
            int sg = 4 * ks + 2 * lh;              // hi seg for this lane's value-group
            unsigned ah[2][4], al[2][4];
#pragma unroll
            for (int mt = 0; mt < 2; mt++) {
                int r = wm * 32 + mt * 16 + lr;
                ldsm4(ah[mt], sA + r * 128 + ((sg ^ (r & 7)) * 16));
                ldsm4(al[mt], sA + r * 128 + (((sg + 1) ^ (r & 7)) * 16));
            }
#pragma unroll
            for (int ntp = 0; ntp < NTP; ntp++) {
                unsigned bh[4], bl[4];
                int rn = wn * (BN / 4) + ntp * 16 + lr;
                ldsm4(bh, sB + rn * 128 + ((sg ^ (rn & 7)) * 16));
                ldsm4(bl, sB + rn * 128 + (((sg + 1) ^ (rn & 7)) * 16));
#pragma unroll
                for (int mt = 0; mt < 2; mt++) {
#pragma unroll
                    for (int ns = 0; ns < 2; ns++) {
                        float* cf = cacc[mt][ntp * 2 + ns];
                        mma16816(cf, ah[mt], bh[ns], bh[ns + 2]);
                        mma16816(cf, ah[mt], bl[ns], bl[ns + 2]);
                        mma16816(cf, al[mt], bh[ns], bh[ns + 2]);
                    }
                }
            }
        }
        __syncthreads();
    }

#pragma unroll
    for (int mt = 0; mt < 2; mt++) {
#pragma unroll
        for (int j = 0; j < NTP * 2; j++) {
            int row = m0 + wm * 32 + mt * 16 + (lane >> 2);
            int col = wn * (BN / 4) + (j >> 1) * 16 + (j & 1) * 8 + (lane & 3) * 2;
            float bx = __ldg(&bias[col]), by = __ldg(&bias[col + 1]);
            if (row < M) {
                float2 o0;
                o0.x = fmaxf(cacc[mt][j][0] + bx, 0.0f);
                o0.y = fmaxf(cacc[mt][j][1] + by, 0.0f);
                *(float2*)(C + (size_t)row * BN + col) = o0;
            }
            if (row + 8 < M) {
                float2 o1;
                o1.x = fmaxf(cacc[mt][j][2] + bx, 0.0f);
                o1.y = fmaxf(cacc[mt][j][3] + by, 0.0f);
                *(float2*)(C + (size_t)(row + 8) * BN + col) = o1;
            }
        }
    }
}

// ---------------- in-place log_softmax over 128 cols ----------------
__global__ void lsm_kernel(float* __restrict__ out) {
    int n = blockIdx.x;
    int t = threadIdx.x;
    float v = out[n * 128 + t];
    float m = v;
#pragma unroll
    for (int o = 16; o > 0; o >>= 1) m = fmaxf(m, __shfl_xor_sync(0xffffffffu, m, o));
    __shared__ float sred[4];
    __shared__ float ssum[4];
    int w = t >> 5, l = t & 31;
    if (l == 0) sred[w] = m;
    __syncthreads();
    float M4 = fmaxf(fmaxf(sred[0], sred[1]), fmaxf(sred[2], sred[3]));
    float e = expf(v - M4);
    float s = e;
#pragma unroll
    for (int o = 16; o > 0; o >>= 1) s += __shfl_xor_sync(0xffffffffu, s, o);
    if (l == 0) ssum[w] = s;
    __syncthreads();
    float S = ssum[0] + ssum[1] + ssum[2] + ssum[3];
    out[n * 128 + t] = v - M4 - logf(S);
}

// ---------------- entry ----------------
extern "C" void kernel_launch(void* const* d_in, const int* in_sizes, int n_in,
                              void* d_out, int out_size) {
    const float* x      = (const float*)d_in[0];
    const int*   ei     = (const int*)  d_in[1];
    const float* pseudo = (const float*)d_in[2];
    const float* W1     = (const float*)d_in[3];
    const float* root1  = (const float*)d_in[4];
    const float* b1     = (const float*)d_in[5];
    const float* W2     = (const float*)d_in[6];
    const float* root2  = (const float*)d_in[7];
    const float* b2     = (const float*)d_in[8];
    const float* W3     = (const float*)d_in[9];
    const float* root3  = (const float*)d_in[10];
    const float* b3     = (const float*)d_in[11];
    float* out = (float*)d_out;
    int N = in_sizes[0];
    int E = in_sizes[1] / 2;

    const int SMEM2 = 2 * (64 * 128 + 64 * 128);    // 32768
    const int SMEM3 = 2 * (64 * 128 + 128 * 128);   // 49152
    cudaFuncSetAttribute(gemm_cp_kernel<1536, 32, 64>,
                         cudaFuncAttributeMaxDynamicSharedMemorySize, SMEM2);
    cudaFuncSetAttribute(gemm_cp_kernel<3072, 64, 128>,
                         cudaFuncAttributeMaxDynamicSharedMemorySize, SMEM3);

    int eb = (E + 255) / 256;
    precompute_kernel<<<eb, 256>>>(pseudo, E);
    hist_kernel<<<eb, 256>>>(ei, E);
    prefix_kernel<<<1, 1024>>>();
    order_kernel<<<eb, 256>>>(ei, E);                    // profiled slot (#4)
    bsplit_kernel<1536, 32, 64><<<(64 * 196 + 255) / 256, 256>>>(W2, root2);
    bsplit_kernel<3072, 64, 128><<<(128 * 392 + 255) / 256, 256>>>(W3, root3);
    scatter1_kernel<<<eb, 256>>>(ei, x, E);
    dense1_kernel<<<(N * 32 + 255) / 256, 256>>>(x, W1, root1, b1, N);
    hsplit_kernel<32><<<(N * 4 + 255) / 256, 256>>>(N);
    gather_scatter_kernel<32><<<N, 32>>>(N);
    gemm_cp_kernel<1536, 32, 64><<<(N + 63) / 64, 256, SMEM2>>>(b2, nullptr, N);
    hsplit_kernel<64><<<(N * 8 + 255) / 256, 256>>>(N);
    gather_scatter_kernel<64><<<N, 64>>>(N);
    gemm_cp_kernel<3072, 64, 128><<<(N + 63) / 64, 256, SMEM3>>>(b3, out, N);
    lsm_kernel<<<N, 128>>>(out);
}